// round 15
// baseline (speedup 1.0000x reference)
#include <cuda_runtime.h>
#include <cuda_bf16.h>
#include <stdint.h>

// Problem constants
#define NN      8192
#define GEV     32
#define PER     256      // nodes per event
#define KK      15
#define FIN     4
#define FOUT    4
#define LATD    64
#define HIDD    128

#define H_ELEMS   (NN * LATD)          // 524288
#define XE_ELEMS  (NN * FOUT)          // 32768
#define NKE       (NN * KK)            // 122880
#define XE_OFF    (H_ELEMS)
#define EI_OFF    (H_ELEMS + XE_ELEMS) // 557056

#define FULLMASK 0xffffffffu
typedef unsigned long long ull;

#if defined(__CUDA_ARCH__) && (__CUDA_ARCH__ >= 900)
#define GRID_DEP_SYNC() cudaGridDependencySynchronize()
#else
#define GRID_DEP_SYNC()
#endif

// Device scratch (no allocations allowed)
__device__ float  g_h0[NN * LATD];
__device__ float  g_h1[NN * LATD];
__device__ int    g_nbr[NN * KK];
__device__ float4 g_pos[NN];

// ---------------------------------------------------------------------------
// Kernel 1: space_emb FFN  h = leaky(x@W1+b1)@W2+b2
// 4 threads per row, 16 output cols each. grid 128 x 256.
// q==0 threads also emit positions (cols 0..2) to g_pos for the kNN kernel.
// ---------------------------------------------------------------------------
__global__ void k_space_emb(const float* __restrict__ x,
                            const float* __restrict__ W1, const float* __restrict__ b1,
                            const float* __restrict__ W2, const float* __restrict__ b2,
                            float* __restrict__ hout,
                            float4* __restrict__ pos) {
    __shared__ float sW1[FIN * LATD];
    __shared__ float sb1[LATD];
    __shared__ float sW2[LATD * LATD];
    __shared__ float sb2[LATD];
    int tid = threadIdx.x;
    for (int i = tid; i < FIN * LATD; i += blockDim.x) sW1[i] = W1[i];
    for (int i = tid; i < LATD; i += blockDim.x) { sb1[i] = b1[i]; sb2[i] = b2[i]; }
    {
        float4* sW24 = (float4*)sW2;
        const float4* W24 = (const float4*)W2;
#pragma unroll
        for (int i = 0; i < (LATD * LATD) / 4 / 256; ++i)
            sW24[tid + i * 256] = W24[tid + i * 256];
    }
    __syncthreads();

    int row = blockIdx.x * 64 + (tid >> 2);
    int q   = tid & 3;
    int c0  = q * 16;

    float4 xi = *(const float4*)&x[row * FIN];

    float acc[16];
#pragma unroll
    for (int c = 0; c < 16; ++c) acc[c] = sb2[c0 + c];

#pragma unroll 4
    for (int j = 0; j < LATD; ++j) {
        float tj = sb1[j]
                 + xi.x * sW1[0 * LATD + j]
                 + xi.y * sW1[1 * LATD + j]
                 + xi.z * sW1[2 * LATD + j]
                 + xi.w * sW1[3 * LATD + j];
        tj = (tj > 0.0f) ? tj : 0.01f * tj;
        const float* w2r = &sW2[j * LATD + c0];
#pragma unroll
        for (int c = 0; c < 16; ++c) acc[c] += tj * w2r[c];
    }
    float* o = &hout[row * LATD + c0];
#pragma unroll
    for (int c = 0; c < 16; ++c) o[c] = acc[c];
    if (q == 0) pos[row] = make_float4(acc[0], acc[1], acc[2], 0.0f);
}

// ---------------------------------------------------------------------------
// Kernel 2: event-local kNN (k=15), 1 warp per query, 1024 threads/CTA,
// grid 256 (32 queries per CTA, 8 CTAs per event).
// Lane owns 8 candidates as packed u64 keys (dist_bits<<8 | local_idx):
// exact (d, idx) lexicographic order == lax.top_k tie-breaking. Lane sorts
// its 8 keys (19-CE Batcher network), then 15 divergence-free
// warp-butterfly u64-min extraction rounds. PDL: waits on space_emb.
// ---------------------------------------------------------------------------
#define CE(i, j) { ull lo = (s##i < s##j) ? s##i : s##j; \
                   ull hi = (s##i < s##j) ? s##j : s##i; \
                   s##i = lo; s##j = hi; }

__global__ void __launch_bounds__(1024, 1)
k_knn(const float4* __restrict__ pos,
      int* __restrict__ nbr,
      float* __restrict__ out_ei) {
    __shared__ float px[PER], py[PER], pz[PER];

    int tid  = threadIdx.x;
    int ev   = blockIdx.x >> 3;
    int oct  = blockIdx.x & 7;
    int base = ev * PER;

    GRID_DEP_SYNC();                   // wait for space_emb's pos

    if (tid < PER) {
        float4 p = pos[base + tid];
        px[tid] = p.x; py[tid] = p.y; pz[tid] = p.z;
    }
    __syncthreads();

    int warp = tid >> 5;               // 0..31 = query within octant
    int lane = tid & 31;
    int lq   = oct * 32 + warp;        // event-local query
    int gid  = base + lq;

    float xi = px[lq], yi = py[lq], zi = pz[lq];

    // 8 packed keys: candidates j = lane + 32*s
    ull s0, s1, s2, s3, s4, s5, s6, s7;
    {
        ull ks[8];
#pragma unroll
        for (int s = 0; s < 8; ++s) {
            int j = lane + 32 * s;
            float dx = __fadd_rn(xi, -px[j]);
            float dy = __fadd_rn(yi, -py[j]);
            float dz = __fadd_rn(zi, -pz[j]);
            float d  = __fadd_rn(__fadd_rn(__fmul_rn(dx, dx),
                                           __fmul_rn(dy, dy)),
                                 __fmul_rn(dz, dz));
            unsigned db = __float_as_uint(d);
            if (j == lq) db = 0x7F800000u;   // +INF: exclude self
            ks[s] = ((ull)db << 8) | (unsigned)j;
        }
        s0 = ks[0]; s1 = ks[1]; s2 = ks[2]; s3 = ks[3];
        s4 = ks[4]; s5 = ks[5]; s6 = ks[6]; s7 = ks[7];
    }

    // sort 8 ascending: Batcher odd-even network, 19 CEs
    CE(0,1) CE(2,3) CE(4,5) CE(6,7)
    CE(0,2) CE(1,3) CE(4,6) CE(5,7)
    CE(1,2) CE(5,6)
    CE(0,4) CE(1,5) CE(2,6) CE(3,7)
    CE(2,4) CE(3,5)
    CE(1,2) CE(3,4) CE(5,6)

    // 15 extract-min rounds, divergence-free
    ull keep = 0;
#pragma unroll
    for (int r = 0; r < KK; ++r) {
        ull w = s0;
#pragma unroll
        for (int off = 16; off > 0; off >>= 1) {
            ull o = __shfl_xor_sync(FULLMASK, w, off);
            if (o < w) w = o;
        }
        if (lane == r) keep = w;
        if (s0 == w) {                 // winner shifts its sorted list down
            s0 = s1; s1 = s2; s2 = s3; s3 = s4;
            s4 = s5; s5 = s6; s6 = s7; s7 = ~0ull;
        }
    }

    // lanes 0..14 hold neighbors in ascending (d, idx) order
    if (lane < KK) {
        int jloc = (int)(keep & 0xFF);
        int gj   = base + jloc;
        int e    = gid * KK + lane;
        nbr[e] = gj;
        out_ei[e]       = (float)gj;
        out_ei[NKE + e] = (float)gid;
    }
}

// ---------------------------------------------------------------------------
// Kernel 3: GIN layer (best config). 256 threads, 32 rows/block, grid 256,
// occupancy 2. Phase B 4x4 tile (a = warp broadcast from transposed mT),
// phase C / OE 4x2 tiles. FUSE_OE epilogue reuses mT (sh) and st (su).
// PDL: weight staging overlaps the predecessor; GRID_DEP_SYNC before gather.
// ---------------------------------------------------------------------------
#define MT_S 36    // mT row stride (k-major, 32 rows + pad)
#define ST_S 132   // st row stride (128 + pad)
#define SH_S 68    // sh row stride (64 + pad), aliased onto mT

template <bool FUSE_OE>
__global__ void __launch_bounds__(256, 2)
k_gin(const float* __restrict__ h_in,
      float* __restrict__ h_out,
      const int* __restrict__ nbr,
      const float* __restrict__ Wa, const float* __restrict__ ba,
      const float* __restrict__ Wb, const float* __restrict__ bb,
      const float* __restrict__ W1o, const float* __restrict__ b1o,
      const float* __restrict__ W2o, const float* __restrict__ b2o,
      float* __restrict__ xe) {
    extern __shared__ float sm[];
    float* sWa  = sm;                    // 8192
    float* sWb  = sWa + 8192;            // 8192
    float* sba  = sWb + 8192;            // 128
    float* sbb  = sba + 128;             // 64
    float* mT   = sbb + 64;              // 64*MT_S = 2304 (reused as sh 32*SH_S)
    float* st   = mT + 64 * MT_S;        // 32*ST_S = 4224 (reused as su)
    float* sW1o = st + 32 * ST_S;        // 4096 (FUSE_OE)
    float* sW2o = sW1o + 4096;           // 256
    float* sb1o = sW2o + 256;            // 64
    float* sb2o = sb1o + 64;             // 4

    int tid = threadIdx.x;
    // ---- stage weights (independent of predecessor — overlaps via PDL) -----
    {
        const float4* Wa4 = (const float4*)Wa;
        const float4* Wb4 = (const float4*)Wb;
        float4* dA = (float4*)sWa;
        float4* dB = (float4*)sWb;
#pragma unroll
        for (int i = 0; i < 8; ++i) {
            dA[tid + i * 256] = Wa4[tid + i * 256];
            dB[tid + i * 256] = Wb4[tid + i * 256];
        }
        if (tid < 128) sba[tid] = ba[tid];
        if (tid < 64)  sbb[tid] = bb[tid];
        if (FUSE_OE) {
            const float4* W1o4 = (const float4*)W1o;
            float4* d3 = (float4*)sW1o;
#pragma unroll
            for (int i = 0; i < 4; ++i) d3[tid + i * 256] = W1o4[tid + i * 256];
            sW2o[tid] = W2o[tid];        // 256 floats exactly
            if (tid < 64) sb1o[tid] = b1o[tid];
            if (tid < 4)  sb2o[tid] = b2o[tid];
        }
    }

    GRID_DEP_SYNC();                   // wait for predecessor's h_in / nbr

    int base = blockIdx.x * 32;

    // ---- Gather: m = h_i + sum of 15 neighbors -> mT[k][row] ---------------
    {
        int r   = tid >> 3;              // 0..31
        int oct = tid & 7;
        int i   = base + r;
        const float4* h4 = (const float4*)h_in;
        const int* nb = &nbr[i * KK];
        float4 a0 = h4[i * 16 + oct * 2];
        float4 a1 = h4[i * 16 + oct * 2 + 1];
#pragma unroll
        for (int s = 0; s < KK; ++s) {
            int j = nb[s];
            float4 v0 = h4[j * 16 + oct * 2];
            float4 v1 = h4[j * 16 + oct * 2 + 1];
            a0.x += v0.x; a0.y += v0.y; a0.z += v0.z; a0.w += v0.w;
            a1.x += v1.x; a1.y += v1.y; a1.z += v1.z; a1.w += v1.w;
        }
        int k0 = oct * 8;
        mT[(k0 + 0) * MT_S + r] = a0.x;
        mT[(k0 + 1) * MT_S + r] = a0.y;
        mT[(k0 + 2) * MT_S + r] = a0.z;
        mT[(k0 + 3) * MT_S + r] = a0.w;
        mT[(k0 + 4) * MT_S + r] = a1.x;
        mT[(k0 + 5) * MT_S + r] = a1.y;
        mT[(k0 + 6) * MT_S + r] = a1.z;
        mT[(k0 + 7) * MT_S + r] = a1.w;
    }
    __syncthreads();

    int r0 = (tid >> 5) * 4;            // warp-uniform row base (0..28)
    int cx = tid & 31;

    // ---- Phase B: t = relu(m @ Wa + ba), thread tile 4x4 -------------------
    {
        int c0 = cx * 4;
        float acc[4][4];
#pragma unroll
        for (int i = 0; i < 4; ++i)
#pragma unroll
            for (int c = 0; c < 4; ++c) acc[i][c] = sba[c0 + c];

#pragma unroll 8
        for (int k = 0; k < 64; ++k) {
            float4 a = *(const float4*)&mT[k * MT_S + r0];     // warp broadcast
            float4 b = *(const float4*)&sWa[k * HIDD + c0];
            acc[0][0] += a.x * b.x; acc[0][1] += a.x * b.y;
            acc[0][2] += a.x * b.z; acc[0][3] += a.x * b.w;
            acc[1][0] += a.y * b.x; acc[1][1] += a.y * b.y;
            acc[1][2] += a.y * b.z; acc[1][3] += a.y * b.w;
            acc[2][0] += a.z * b.x; acc[2][1] += a.z * b.y;
            acc[2][2] += a.z * b.z; acc[2][3] += a.z * b.w;
            acc[3][0] += a.w * b.x; acc[3][1] += a.w * b.y;
            acc[3][2] += a.w * b.z; acc[3][3] += a.w * b.w;
        }
#pragma unroll
        for (int i = 0; i < 4; ++i) {
            float4 q;
            q.x = fmaxf(acc[i][0], 0.f);
            q.y = fmaxf(acc[i][1], 0.f);
            q.z = fmaxf(acc[i][2], 0.f);
            q.w = fmaxf(acc[i][3], 0.f);
            *(float4*)&st[(r0 + i) * ST_S + c0] = q;
        }
    }
    __syncthreads();

    // ---- Phase C: h_out = h_in + t @ Wb + bb, thread tile 4x2 --------------
    int c1 = cx * 2;
    {
        float acc2[4][2];
#pragma unroll
        for (int i = 0; i < 4; ++i) { acc2[i][0] = sbb[c1]; acc2[i][1] = sbb[c1 + 1]; }

#pragma unroll 4
        for (int k2 = 0; k2 < HIDD; k2 += 4) {
            float4 ar[4];
            float2 bk[4];
#pragma unroll
            for (int i = 0; i < 4; ++i) ar[i] = *(const float4*)&st[(r0 + i) * ST_S + k2];
#pragma unroll
            for (int j = 0; j < 4; ++j) bk[j] = *(const float2*)&sWb[(k2 + j) * LATD + c1];
#pragma unroll
            for (int i = 0; i < 4; ++i) {
                acc2[i][0] += ar[i].x * bk[0].x + ar[i].y * bk[1].x
                            + ar[i].z * bk[2].x + ar[i].w * bk[3].x;
                acc2[i][1] += ar[i].x * bk[0].y + ar[i].y * bk[1].y
                            + ar[i].z * bk[2].y + ar[i].w * bk[3].y;
            }
        }
#pragma unroll
        for (int i = 0; i < 4; ++i) {
            float2 hv = *(const float2*)&h_in[(base + r0 + i) * LATD + c1];
            float2 o;
            o.x = hv.x + acc2[i][0];
            o.y = hv.y + acc2[i][1];
            *(float2*)&h_out[(base + r0 + i) * LATD + c1] = o;
            if (FUSE_OE) *(float2*)&mT[(r0 + i) * SH_S + c1] = o;  // sh = mT reuse
        }
    }

    if (FUSE_OE) {
        __syncthreads();
        // ---- OE1: u = leaky(h @ W1o + b1o), thread tile 4x2 (sh=mT) --------
        float u[4][2];
#pragma unroll
        for (int i = 0; i < 4; ++i) { u[i][0] = sb1o[c1]; u[i][1] = sb1o[c1 + 1]; }
#pragma unroll 4
        for (int k = 0; k < LATD; k += 4) {
            float4 ar[4];
            float2 bk[4];
#pragma unroll
            for (int i = 0; i < 4; ++i) ar[i] = *(const float4*)&mT[(r0 + i) * SH_S + k];
#pragma unroll
            for (int j = 0; j < 4; ++j) bk[j] = *(const float2*)&sW1o[(k + j) * LATD + c1];
#pragma unroll
            for (int i = 0; i < 4; ++i) {
                u[i][0] += ar[i].x * bk[0].x + ar[i].y * bk[1].x
                         + ar[i].z * bk[2].x + ar[i].w * bk[3].x;
                u[i][1] += ar[i].x * bk[0].y + ar[i].y * bk[1].y
                         + ar[i].z * bk[2].y + ar[i].w * bk[3].y;
            }
        }
#pragma unroll
        for (int i = 0; i < 4; ++i) {
            float2 q;
            q.x = (u[i][0] > 0.f) ? u[i][0] : 0.01f * u[i][0];
            q.y = (u[i][1] > 0.f) ? u[i][1] : 0.01f * u[i][1];
            *(float2*)&st[(r0 + i) * ST_S + c1] = q;   // su = st reuse
        }
        __syncthreads();
        // ---- OE2: x_emb = u @ W2o + b2o; 128 threads = (row, feature) ------
        if (tid < 128) {
            int row = tid >> 2;
            int oc  = tid & 3;
            float a = sb2o[oc];
#pragma unroll 8
            for (int k = 0; k < LATD; ++k)
                a += st[row * ST_S + k] * sW2o[k * FOUT + oc];
            xe[(base + row) * FOUT + oc] = a;
        }
    }
}

// ---------------------------------------------------------------------------
extern "C" void kernel_launch(void* const* d_in, const int* in_sizes, int n_in,
                              void* d_out, int out_size) {
    const float* x     = (const float*)d_in[0];
    const float* W_se1 = (const float*)d_in[3];
    const float* b_se1 = (const float*)d_in[4];
    const float* W_se2 = (const float*)d_in[5];
    const float* b_se2 = (const float*)d_in[6];
    const float* W_g1a = (const float*)d_in[7];
    const float* b_g1a = (const float*)d_in[8];
    const float* W_g1b = (const float*)d_in[9];
    const float* b_g1b = (const float*)d_in[10];
    const float* W_g2a = (const float*)d_in[11];
    const float* b_g2a = (const float*)d_in[12];
    const float* W_g2b = (const float*)d_in[13];
    const float* b_g2b = (const float*)d_in[14];
    const float* W_oe1 = (const float*)d_in[15];
    const float* b_oe1 = (const float*)d_in[16];
    const float* W_oe2 = (const float*)d_in[17];
    const float* b_oe2 = (const float*)d_in[18];

    float* out    = (float*)d_out;
    float* out_h  = out;
    float* out_xe = out + XE_OFF;
    float* out_ei = out + EI_OFF;

    void *p_h0, *p_h1, *p_nbr, *p_pos;
    cudaGetSymbolAddress(&p_h0, g_h0);
    cudaGetSymbolAddress(&p_h1, g_h1);
    cudaGetSymbolAddress(&p_nbr, g_nbr);
    cudaGetSymbolAddress(&p_pos, g_pos);
    float*  h0  = (float*)p_h0;
    float*  h1  = (float*)p_h1;
    int*    nb  = (int*)p_nbr;
    float4* pos = (float4*)p_pos;

    static const size_t gin_smem_base =
        (size_t)(8192 + 8192 + 128 + 64 + 64 * MT_S + 32 * ST_S) * sizeof(float);
    static const size_t gin_smem_oe = gin_smem_base +
        (size_t)(4096 + 256 + 64 + 4) * sizeof(float);
    cudaFuncSetAttribute(k_gin<false>, cudaFuncAttributeMaxDynamicSharedMemorySize,
                         (int)gin_smem_base);
    cudaFuncSetAttribute(k_gin<true>, cudaFuncAttributeMaxDynamicSharedMemorySize,
                         (int)gin_smem_oe);

    // PDL launch attribute: allow overlap with predecessor's tail
    cudaLaunchAttribute pdl[1];
    pdl[0].id = cudaLaunchAttributeProgrammaticStreamSerialization;
    pdl[0].val.programmaticStreamSerializationAllowed = 1;

    // 1) space_emb -> h0 (+ positions), plain launch
    k_space_emb<<<NN / 64, 256>>>(x, W_se1, b_se1, W_se2, b_se2, h0, pos);

    // 2) kNN (PDL)
    {
        cudaLaunchConfig_t cfg = {};
        cfg.gridDim = dim3(GEV * 8);
        cfg.blockDim = dim3(1024);
        cfg.dynamicSmemBytes = 0;
        cfg.stream = 0;
        cfg.attrs = pdl;
        cfg.numAttrs = 1;
        cudaLaunchKernelEx(&cfg, k_knn, (const float4*)pos, nb, out_ei);
    }

    // 3) GIN layer 1 (PDL): h0 -> h1
    {
        cudaLaunchConfig_t cfg = {};
        cfg.gridDim = dim3(NN / 32);
        cfg.blockDim = dim3(256);
        cfg.dynamicSmemBytes = gin_smem_base;
        cfg.stream = 0;
        cfg.attrs = pdl;
        cfg.numAttrs = 1;
        cudaLaunchKernelEx(&cfg, k_gin<false>,
                           (const float*)h0, h1, (const int*)nb,
                           W_g1a, b_g1a, W_g1b, b_g1b,
                           (const float*)nullptr, (const float*)nullptr,
                           (const float*)nullptr, (const float*)nullptr,
                           (float*)nullptr);
    }

    // 4) GIN layer 2 + fused out_emb (PDL): h1 -> d_out, x_emb -> d_out
    {
        cudaLaunchConfig_t cfg = {};
        cfg.gridDim = dim3(NN / 32);
        cfg.blockDim = dim3(256);
        cfg.dynamicSmemBytes = gin_smem_oe;
        cfg.stream = 0;
        cfg.attrs = pdl;
        cfg.numAttrs = 1;
        cudaLaunchKernelEx(&cfg, k_gin<true>,
                           (const float*)h1, out_h, (const int*)nb,
                           W_g2a, b_g2a, W_g2b, b_g2b,
                           W_oe1, b_oe1, W_oe2, b_oe2, out_xe);
    }
}

// round 16
// speedup vs baseline: 1.0005x; 1.0005x over previous
#include <cuda_runtime.h>
#include <cuda_bf16.h>
#include <stdint.h>

// Problem constants
#define NN      8192
#define GEV     32
#define PER     256      // nodes per event
#define KK      15
#define FIN     4
#define FOUT    4
#define LATD    64
#define HIDD    128

#define H_ELEMS   (NN * LATD)          // 524288
#define XE_ELEMS  (NN * FOUT)          // 32768
#define NKE       (NN * KK)            // 122880
#define XE_OFF    (H_ELEMS)
#define EI_OFF    (H_ELEMS + XE_ELEMS) // 557056

#define FULLMASK 0xffffffffu
typedef unsigned long long ull;

// Device scratch (no allocations allowed)
__device__ float g_h0[NN * LATD];
__device__ float g_h1[NN * LATD];
__device__ int   g_nbr[NN * KK];

// ---------------------------------------------------------------------------
// Kernel 1: fused space_emb + event-local kNN, 1024 threads/CTA, grid 256.
// CTA = one 32-query octant (8 CTAs/event).
//  part 1: space_emb for own 32 rows -> h0 (32 thr/row, 2 cols each).
//  part 2: positions (emb cols 0..2) for ALL 256 event rows (1 thr/row),
//          recomputed with identical math -> consistent top-k selection.
//  part 3: kNN, 1 warp/query: lane packs 8 keys (dist_bits<<8 | idx) = exact
//          lax.top_k (d, idx) order; 19-CE Batcher sort; 15 divergence-free
//          warp-butterfly u64-min extraction rounds.
// ---------------------------------------------------------------------------
#define CE(i, j) { ull lo = (s##i < s##j) ? s##i : s##j; \
                   ull hi = (s##i < s##j) ? s##j : s##i; \
                   s##i = lo; s##j = hi; }

__global__ void __launch_bounds__(1024, 1)
k_se_knn(const float* __restrict__ x,
         const float* __restrict__ W1, const float* __restrict__ b1,
         const float* __restrict__ W2, const float* __restrict__ b2,
         float* __restrict__ hout,
         int* __restrict__ nbr,
         float* __restrict__ out_ei) {
    __shared__ float sW1[FIN * LATD];
    __shared__ float sb1[LATD];
    __shared__ float sb2[LATD];
    __shared__ float sW2[LATD * LATD];
    __shared__ float px[PER], py[PER], pz[PER];

    int tid  = threadIdx.x;
    int ev   = blockIdx.x >> 3;
    int oct  = blockIdx.x & 7;
    int base = ev * PER;

    // ---- stage weights ------------------------------------------------------
    if (tid < FIN * LATD) sW1[tid] = W1[tid];
    if (tid < 64) sb1[tid] = b1[tid];
    else if (tid >= 64 && tid < 128) sb2[tid - 64] = b2[tid - 64];
    ((float4*)sW2)[tid] = ((const float4*)W2)[tid];   // 4096 floats = 1024 f4
    __syncthreads();

    // ---- part 1: space_emb for own 32 rows (32 thr/row, 2 cols each) -------
    {
        int lrow = oct * 32 + (tid >> 5);
        int row  = base + lrow;
        int c0   = (tid & 31) * 2;

        float4 xi = *(const float4*)&x[row * FIN];

        float a0 = sb2[c0], a1 = sb2[c0 + 1];
#pragma unroll 4
        for (int j = 0; j < LATD; ++j) {
            float tj = sb1[j]
                     + xi.x * sW1[0 * LATD + j]
                     + xi.y * sW1[1 * LATD + j]
                     + xi.z * sW1[2 * LATD + j]
                     + xi.w * sW1[3 * LATD + j];
            tj = (tj > 0.0f) ? tj : 0.01f * tj;
            const float* w2r = &sW2[j * LATD + c0];
            a0 += tj * w2r[0];
            a1 += tj * w2r[1];
        }
        hout[row * LATD + c0]     = a0;
        hout[row * LATD + c0 + 1] = a1;
    }

    // ---- part 2: positions for all 256 event rows (1 thr/row) --------------
    if (tid < PER) {
        int n   = tid;
        int row = base + n;
        float4 xi = *(const float4*)&x[row * FIN];
        float ax = 0.f, ay = 0.f, az = 0.f;
#pragma unroll 4
        for (int j = 0; j < LATD; ++j) {
            float tj = sb1[j]
                     + xi.x * sW1[0 * LATD + j]
                     + xi.y * sW1[1 * LATD + j]
                     + xi.z * sW1[2 * LATD + j]
                     + xi.w * sW1[3 * LATD + j];
            tj = (tj > 0.0f) ? tj : 0.01f * tj;
            const float* w2r = &sW2[j * LATD];
            ax += tj * w2r[0];
            ay += tj * w2r[1];
            az += tj * w2r[2];
        }
        px[n] = ax + sb2[0];
        py[n] = ay + sb2[1];
        pz[n] = az + sb2[2];
    }
    __syncthreads();   // positions ready

    // ---- part 3: kNN, 1 warp per query --------------------------------------
    {
        int warp = tid >> 5;               // 0..31 = query within octant
        int lane = tid & 31;
        int lq   = oct * 32 + warp;
        int gid  = base + lq;

        float xi = px[lq], yi = py[lq], zi = pz[lq];

        // 8 packed keys: candidates j = lane + 32*s
        ull s0, s1, s2, s3, s4, s5, s6, s7;
        {
            ull ks[8];
#pragma unroll
            for (int s = 0; s < 8; ++s) {
                int j = lane + 32 * s;
                float dx = __fadd_rn(xi, -px[j]);
                float dy = __fadd_rn(yi, -py[j]);
                float dz = __fadd_rn(zi, -pz[j]);
                float d  = __fadd_rn(__fadd_rn(__fmul_rn(dx, dx),
                                               __fmul_rn(dy, dy)),
                                     __fmul_rn(dz, dz));
                unsigned db = __float_as_uint(d);
                if (j == lq) db = 0x7F800000u;   // +INF: exclude self
                ks[s] = ((ull)db << 8) | (unsigned)j;
            }
            s0 = ks[0]; s1 = ks[1]; s2 = ks[2]; s3 = ks[3];
            s4 = ks[4]; s5 = ks[5]; s6 = ks[6]; s7 = ks[7];
        }

        // sort 8 ascending: Batcher odd-even network, 19 CEs
        CE(0,1) CE(2,3) CE(4,5) CE(6,7)
        CE(0,2) CE(1,3) CE(4,6) CE(5,7)
        CE(1,2) CE(5,6)
        CE(0,4) CE(1,5) CE(2,6) CE(3,7)
        CE(2,4) CE(3,5)
        CE(1,2) CE(3,4) CE(5,6)

        // 15 extract-min rounds, divergence-free
        ull keep = 0;
#pragma unroll
        for (int r = 0; r < KK; ++r) {
            ull w = s0;
#pragma unroll
            for (int off = 16; off > 0; off >>= 1) {
                ull o = __shfl_xor_sync(FULLMASK, w, off);
                if (o < w) w = o;
            }
            if (lane == r) keep = w;
            if (s0 == w) {                 // winner shifts its sorted list
                s0 = s1; s1 = s2; s2 = s3; s3 = s4;
                s4 = s5; s5 = s6; s6 = s7; s7 = ~0ull;
            }
        }

        if (lane < KK) {
            int jloc = (int)(keep & 0xFF);
            int gj   = base + jloc;
            int e    = gid * KK + lane;
            nbr[e] = gj;
            out_ei[e]       = (float)gj;
            out_ei[NKE + e] = (float)gid;
        }
    }
}

// ---------------------------------------------------------------------------
// Kernel 2: GIN layer (best config, R14). 256 threads, 32 rows/block,
// grid 256, occupancy 2. Phase B 4x4 tile (a = warp broadcast from transposed
// mT), phase C / OE 4x2 tiles. FUSE_OE epilogue reuses mT (sh) and st (su).
// ---------------------------------------------------------------------------
#define MT_S 36    // mT row stride (k-major, 32 rows + pad)
#define ST_S 132   // st row stride (128 + pad)
#define SH_S 68    // sh row stride (64 + pad), aliased onto mT

template <bool FUSE_OE>
__global__ void __launch_bounds__(256, 2)
k_gin(const float* __restrict__ h_in,
      float* __restrict__ h_out,
      const int* __restrict__ nbr,
      const float* __restrict__ Wa, const float* __restrict__ ba,
      const float* __restrict__ Wb, const float* __restrict__ bb,
      const float* __restrict__ W1o, const float* __restrict__ b1o,
      const float* __restrict__ W2o, const float* __restrict__ b2o,
      float* __restrict__ xe) {
    extern __shared__ float sm[];
    float* sWa  = sm;                    // 8192
    float* sWb  = sWa + 8192;            // 8192
    float* sba  = sWb + 8192;            // 128
    float* sbb  = sba + 128;             // 64
    float* mT   = sbb + 64;              // 64*MT_S = 2304 (reused as sh 32*SH_S)
    float* st   = mT + 64 * MT_S;        // 32*ST_S = 4224 (reused as su)
    float* sW1o = st + 32 * ST_S;        // 4096 (FUSE_OE)
    float* sW2o = sW1o + 4096;           // 256
    float* sb1o = sW2o + 256;            // 64
    float* sb2o = sb1o + 64;             // 4

    int tid = threadIdx.x;
    // ---- stage weights (row-major, vectorized) -----------------------------
    {
        const float4* Wa4 = (const float4*)Wa;
        const float4* Wb4 = (const float4*)Wb;
        float4* dA = (float4*)sWa;
        float4* dB = (float4*)sWb;
#pragma unroll
        for (int i = 0; i < 8; ++i) {
            dA[tid + i * 256] = Wa4[tid + i * 256];
            dB[tid + i * 256] = Wb4[tid + i * 256];
        }
        if (tid < 128) sba[tid] = ba[tid];
        if (tid < 64)  sbb[tid] = bb[tid];
        if (FUSE_OE) {
            const float4* W1o4 = (const float4*)W1o;
            float4* d3 = (float4*)sW1o;
#pragma unroll
            for (int i = 0; i < 4; ++i) d3[tid + i * 256] = W1o4[tid + i * 256];
            sW2o[tid] = W2o[tid];        // 256 floats exactly
            if (tid < 64) sb1o[tid] = b1o[tid];
            if (tid < 4)  sb2o[tid] = b2o[tid];
        }
    }

    int base = blockIdx.x * 32;

    // ---- Gather: m = h_i + sum of 15 neighbors -> mT[k][row] ---------------
    {
        int r   = tid >> 3;              // 0..31
        int oct = tid & 7;
        int i   = base + r;
        const float4* h4 = (const float4*)h_in;
        const int* nb = &nbr[i * KK];
        float4 a0 = h4[i * 16 + oct * 2];
        float4 a1 = h4[i * 16 + oct * 2 + 1];
#pragma unroll
        for (int s = 0; s < KK; ++s) {
            int j = nb[s];
            float4 v0 = h4[j * 16 + oct * 2];
            float4 v1 = h4[j * 16 + oct * 2 + 1];
            a0.x += v0.x; a0.y += v0.y; a0.z += v0.z; a0.w += v0.w;
            a1.x += v1.x; a1.y += v1.y; a1.z += v1.z; a1.w += v1.w;
        }
        int k0 = oct * 8;
        mT[(k0 + 0) * MT_S + r] = a0.x;
        mT[(k0 + 1) * MT_S + r] = a0.y;
        mT[(k0 + 2) * MT_S + r] = a0.z;
        mT[(k0 + 3) * MT_S + r] = a0.w;
        mT[(k0 + 4) * MT_S + r] = a1.x;
        mT[(k0 + 5) * MT_S + r] = a1.y;
        mT[(k0 + 6) * MT_S + r] = a1.z;
        mT[(k0 + 7) * MT_S + r] = a1.w;
    }
    __syncthreads();

    int r0 = (tid >> 5) * 4;            // warp-uniform row base (0..28)
    int cx = tid & 31;

    // ---- Phase B: t = relu(m @ Wa + ba), thread tile 4x4 -------------------
    {
        int c0 = cx * 4;
        float acc[4][4];
#pragma unroll
        for (int i = 0; i < 4; ++i)
#pragma unroll
            for (int c = 0; c < 4; ++c) acc[i][c] = sba[c0 + c];

#pragma unroll 8
        for (int k = 0; k < 64; ++k) {
            float4 a = *(const float4*)&mT[k * MT_S + r0];     // warp broadcast
            float4 b = *(const float4*)&sWa[k * HIDD + c0];
            acc[0][0] += a.x * b.x; acc[0][1] += a.x * b.y;
            acc[0][2] += a.x * b.z; acc[0][3] += a.x * b.w;
            acc[1][0] += a.y * b.x; acc[1][1] += a.y * b.y;
            acc[1][2] += a.y * b.z; acc[1][3] += a.y * b.w;
            acc[2][0] += a.z * b.x; acc[2][1] += a.z * b.y;
            acc[2][2] += a.z * b.z; acc[2][3] += a.z * b.w;
            acc[3][0] += a.w * b.x; acc[3][1] += a.w * b.y;
            acc[3][2] += a.w * b.z; acc[3][3] += a.w * b.w;
        }
#pragma unroll
        for (int i = 0; i < 4; ++i) {
            float4 q;
            q.x = fmaxf(acc[i][0], 0.f);
            q.y = fmaxf(acc[i][1], 0.f);
            q.z = fmaxf(acc[i][2], 0.f);
            q.w = fmaxf(acc[i][3], 0.f);
            *(float4*)&st[(r0 + i) * ST_S + c0] = q;
        }
    }
    __syncthreads();

    // ---- Phase C: h_out = h_in + t @ Wb + bb, thread tile 4x2 --------------
    int c1 = cx * 2;
    {
        float acc2[4][2];
#pragma unroll
        for (int i = 0; i < 4; ++i) { acc2[i][0] = sbb[c1]; acc2[i][1] = sbb[c1 + 1]; }

#pragma unroll 4
        for (int k2 = 0; k2 < HIDD; k2 += 4) {
            float4 ar[4];
            float2 bk[4];
#pragma unroll
            for (int i = 0; i < 4; ++i) ar[i] = *(const float4*)&st[(r0 + i) * ST_S + k2];
#pragma unroll
            for (int j = 0; j < 4; ++j) bk[j] = *(const float2*)&sWb[(k2 + j) * LATD + c1];
#pragma unroll
            for (int i = 0; i < 4; ++i) {
                acc2[i][0] += ar[i].x * bk[0].x + ar[i].y * bk[1].x
                            + ar[i].z * bk[2].x + ar[i].w * bk[3].x;
                acc2[i][1] += ar[i].x * bk[0].y + ar[i].y * bk[1].y
                            + ar[i].z * bk[2].y + ar[i].w * bk[3].y;
            }
        }
#pragma unroll
        for (int i = 0; i < 4; ++i) {
            float2 hv = *(const float2*)&h_in[(base + r0 + i) * LATD + c1];
            float2 o;
            o.x = hv.x + acc2[i][0];
            o.y = hv.y + acc2[i][1];
            *(float2*)&h_out[(base + r0 + i) * LATD + c1] = o;
            if (FUSE_OE) *(float2*)&mT[(r0 + i) * SH_S + c1] = o;  // sh = mT reuse
        }
    }

    if (FUSE_OE) {
        __syncthreads();
        // ---- OE1: u = leaky(h @ W1o + b1o), thread tile 4x2 (sh=mT) --------
        float u[4][2];
#pragma unroll
        for (int i = 0; i < 4; ++i) { u[i][0] = sb1o[c1]; u[i][1] = sb1o[c1 + 1]; }
#pragma unroll 4
        for (int k = 0; k < LATD; k += 4) {
            float4 ar[4];
            float2 bk[4];
#pragma unroll
            for (int i = 0; i < 4; ++i) ar[i] = *(const float4*)&mT[(r0 + i) * SH_S + k];
#pragma unroll
            for (int j = 0; j < 4; ++j) bk[j] = *(const float2*)&sW1o[(k + j) * LATD + c1];
#pragma unroll
            for (int i = 0; i < 4; ++i) {
                u[i][0] += ar[i].x * bk[0].x + ar[i].y * bk[1].x
                         + ar[i].z * bk[2].x + ar[i].w * bk[3].x;
                u[i][1] += ar[i].x * bk[0].y + ar[i].y * bk[1].y
                         + ar[i].z * bk[2].y + ar[i].w * bk[3].y;
            }
        }
#pragma unroll
        for (int i = 0; i < 4; ++i) {
            float2 q;
            q.x = (u[i][0] > 0.f) ? u[i][0] : 0.01f * u[i][0];
            q.y = (u[i][1] > 0.f) ? u[i][1] : 0.01f * u[i][1];
            *(float2*)&st[(r0 + i) * ST_S + c1] = q;   // su = st reuse
        }
        __syncthreads();
        // ---- OE2: x_emb = u @ W2o + b2o; 128 threads = (row, feature) ------
        if (tid < 128) {
            int row = tid >> 2;
            int oc  = tid & 3;
            float a = sb2o[oc];
#pragma unroll 8
            for (int k = 0; k < LATD; ++k)
                a += st[row * ST_S + k] * sW2o[k * FOUT + oc];
            xe[(base + row) * FOUT + oc] = a;
        }
    }
}

// ---------------------------------------------------------------------------
extern "C" void kernel_launch(void* const* d_in, const int* in_sizes, int n_in,
                              void* d_out, int out_size) {
    const float* x     = (const float*)d_in[0];
    const float* W_se1 = (const float*)d_in[3];
    const float* b_se1 = (const float*)d_in[4];
    const float* W_se2 = (const float*)d_in[5];
    const float* b_se2 = (const float*)d_in[6];
    const float* W_g1a = (const float*)d_in[7];
    const float* b_g1a = (const float*)d_in[8];
    const float* W_g1b = (const float*)d_in[9];
    const float* b_g1b = (const float*)d_in[10];
    const float* W_g2a = (const float*)d_in[11];
    const float* b_g2a = (const float*)d_in[12];
    const float* W_g2b = (const float*)d_in[13];
    const float* b_g2b = (const float*)d_in[14];
    const float* W_oe1 = (const float*)d_in[15];
    const float* b_oe1 = (const float*)d_in[16];
    const float* W_oe2 = (const float*)d_in[17];
    const float* b_oe2 = (const float*)d_in[18];

    float* out    = (float*)d_out;
    float* out_h  = out;
    float* out_xe = out + XE_OFF;
    float* out_ei = out + EI_OFF;

    void *p_h0, *p_h1, *p_nbr;
    cudaGetSymbolAddress(&p_h0, g_h0);
    cudaGetSymbolAddress(&p_h1, g_h1);
    cudaGetSymbolAddress(&p_nbr, g_nbr);
    float* h0 = (float*)p_h0;
    float* h1 = (float*)p_h1;
    int*   nb = (int*)p_nbr;

    static const size_t gin_smem_base =
        (size_t)(8192 + 8192 + 128 + 64 + 64 * MT_S + 32 * ST_S) * sizeof(float);
    static const size_t gin_smem_oe = gin_smem_base +
        (size_t)(4096 + 256 + 64 + 4) * sizeof(float);
    cudaFuncSetAttribute(k_gin<false>, cudaFuncAttributeMaxDynamicSharedMemorySize,
                         (int)gin_smem_base);
    cudaFuncSetAttribute(k_gin<true>, cudaFuncAttributeMaxDynamicSharedMemorySize,
                         (int)gin_smem_oe);

    // 1) fused space_emb + kNN -> h0, nbr, ei
    k_se_knn<<<GEV * 8, 1024>>>(x, W_se1, b_se1, W_se2, b_se2, h0, nb, out_ei);
    // 2) GIN layer 1: h0 -> h1
    k_gin<false><<<NN / 32, 256, gin_smem_base>>>(h0, h1, nb,
        W_g1a, b_g1a, W_g1b, b_g1b, nullptr, nullptr, nullptr, nullptr, nullptr);
    // 3) GIN layer 2 + fused out_emb: h1 -> d_out (h), x_emb -> d_out
    k_gin<true><<<NN / 32, 256, gin_smem_oe>>>(h1, out_h, nb,
        W_g2a, b_g2a, W_g2b, b_g2b, W_oe1, b_oe1, W_oe2, b_oe2, out_xe);
}

// round 17
// speedup vs baseline: 1.0340x; 1.0335x over previous
#include <cuda_runtime.h>
#include <cuda_bf16.h>
#include <stdint.h>

// Problem constants
#define NN      8192
#define GEV     32
#define PER     256      // nodes per event
#define KK      15
#define FIN     4
#define FOUT    4
#define LATD    64
#define HIDD    128

#define H_ELEMS   (NN * LATD)          // 524288
#define XE_ELEMS  (NN * FOUT)          // 32768
#define NKE       (NN * KK)            // 122880
#define XE_OFF    (H_ELEMS)
#define EI_OFF    (H_ELEMS + XE_ELEMS) // 557056

#define FULLMASK 0xffffffffu
typedef unsigned long long ull;

// Device scratch (no allocations allowed)
__device__ float  g_h0[NN * LATD];
__device__ float  g_h1[NN * LATD];
__device__ int    g_nbr[NN * KK];
__device__ float4 g_pos[NN];

// ---------------------------------------------------------------------------
// Kernel 1: space_emb FFN  h = leaky(x@W1+b1)@W2+b2
// grid 256 x 128 (32 rows/CTA, 4 threads/row, 16 cols each) — covers all SMs.
// q==0 threads also emit positions (cols 0..2) to g_pos for the kNN kernel.
// ---------------------------------------------------------------------------
__global__ void __launch_bounds__(128, 4)
k_space_emb(const float* __restrict__ x,
            const float* __restrict__ W1, const float* __restrict__ b1,
            const float* __restrict__ W2, const float* __restrict__ b2,
            float* __restrict__ hout,
            float4* __restrict__ pos) {
    __shared__ float sW1[FIN * LATD];
    __shared__ float sb1[LATD];
    __shared__ float sW2[LATD * LATD];
    __shared__ float sb2[LATD];
    int tid = threadIdx.x;
    for (int i = tid; i < FIN * LATD; i += blockDim.x) sW1[i] = W1[i];
    for (int i = tid; i < LATD; i += blockDim.x) { sb1[i] = b1[i]; sb2[i] = b2[i]; }
    {
        float4* sW24 = (float4*)sW2;
        const float4* W24 = (const float4*)W2;
#pragma unroll
        for (int i = 0; i < (LATD * LATD) / 4 / 128; ++i)
            sW24[tid + i * 128] = W24[tid + i * 128];
    }
    __syncthreads();

    int row = blockIdx.x * 32 + (tid >> 2);
    int q   = tid & 3;
    int c0  = q * 16;

    float4 xi = *(const float4*)&x[row * FIN];

    float acc[16];
#pragma unroll
    for (int c = 0; c < 16; ++c) acc[c] = sb2[c0 + c];

#pragma unroll 8
    for (int j = 0; j < LATD; ++j) {
        float tj = sb1[j]
                 + xi.x * sW1[0 * LATD + j]
                 + xi.y * sW1[1 * LATD + j]
                 + xi.z * sW1[2 * LATD + j]
                 + xi.w * sW1[3 * LATD + j];
        tj = (tj > 0.0f) ? tj : 0.01f * tj;
        const float* w2r = &sW2[j * LATD + c0];
#pragma unroll
        for (int c = 0; c < 16; ++c) acc[c] += tj * w2r[c];
    }
    float* o = &hout[row * LATD + c0];
#pragma unroll
    for (int c = 0; c < 16; ++c) o[c] = acc[c];
    if (q == 0) pos[row] = make_float4(acc[0], acc[1], acc[2], 0.0f);
}

// ---------------------------------------------------------------------------
// Kernel 2: event-local kNN (k=15), 1 warp per query, 1024 threads/CTA,
// grid 256 (32 queries per CTA, 8 CTAs per event).
// Lane owns 8 candidates as packed u64 keys (dist_bits<<8 | local_idx):
// exact (d, idx) lexicographic order == lax.top_k tie-breaking. Lane sorts
// its 8 keys (19-CE Batcher network), then 15 divergence-free
// warp-butterfly u64-min extraction rounds.
// ---------------------------------------------------------------------------
#define CE(i, j) { ull lo = (s##i < s##j) ? s##i : s##j; \
                   ull hi = (s##i < s##j) ? s##j : s##i; \
                   s##i = lo; s##j = hi; }

__global__ void __launch_bounds__(1024, 1)
k_knn(const float4* __restrict__ pos,
      int* __restrict__ nbr,
      float* __restrict__ out_ei) {
    __shared__ float px[PER], py[PER], pz[PER];

    int tid  = threadIdx.x;
    int ev   = blockIdx.x >> 3;
    int oct  = blockIdx.x & 7;
    int base = ev * PER;

    if (tid < PER) {
        float4 p = pos[base + tid];
        px[tid] = p.x; py[tid] = p.y; pz[tid] = p.z;
    }
    __syncthreads();

    int warp = tid >> 5;               // 0..31 = query within octant
    int lane = tid & 31;
    int lq   = oct * 32 + warp;        // event-local query
    int gid  = base + lq;

    float xi = px[lq], yi = py[lq], zi = pz[lq];

    // 8 packed keys: candidates j = lane + 32*s
    ull s0, s1, s2, s3, s4, s5, s6, s7;
    {
        ull ks[8];
#pragma unroll
        for (int s = 0; s < 8; ++s) {
            int j = lane + 32 * s;
            float dx = __fadd_rn(xi, -px[j]);
            float dy = __fadd_rn(yi, -py[j]);
            float dz = __fadd_rn(zi, -pz[j]);
            float d  = __fadd_rn(__fadd_rn(__fmul_rn(dx, dx),
                                           __fmul_rn(dy, dy)),
                                 __fmul_rn(dz, dz));
            unsigned db = __float_as_uint(d);
            if (j == lq) db = 0x7F800000u;   // +INF: exclude self
            ks[s] = ((ull)db << 8) | (unsigned)j;
        }
        s0 = ks[0]; s1 = ks[1]; s2 = ks[2]; s3 = ks[3];
        s4 = ks[4]; s5 = ks[5]; s6 = ks[6]; s7 = ks[7];
    }

    // sort 8 ascending: Batcher odd-even network, 19 CEs
    CE(0,1) CE(2,3) CE(4,5) CE(6,7)
    CE(0,2) CE(1,3) CE(4,6) CE(5,7)
    CE(1,2) CE(5,6)
    CE(0,4) CE(1,5) CE(2,6) CE(3,7)
    CE(2,4) CE(3,5)
    CE(1,2) CE(3,4) CE(5,6)

    // 15 extract-min rounds, divergence-free
    ull keep = 0;
#pragma unroll
    for (int r = 0; r < KK; ++r) {
        ull w = s0;
#pragma unroll
        for (int off = 16; off > 0; off >>= 1) {
            ull o = __shfl_xor_sync(FULLMASK, w, off);
            if (o < w) w = o;
        }
        if (lane == r) keep = w;
        if (s0 == w) {                 // winner shifts its sorted list down
            s0 = s1; s1 = s2; s2 = s3; s3 = s4;
            s4 = s5; s5 = s6; s6 = s7; s7 = ~0ull;
        }
    }

    // lanes 0..14 hold neighbors in ascending (d, idx) order
    if (lane < KK) {
        int jloc = (int)(keep & 0xFF);
        int gj   = base + jloc;
        int e    = gid * KK + lane;
        nbr[e] = gj;
        out_ei[e]       = (float)gj;
        out_ei[NKE + e] = (float)gid;
    }
}

// ---------------------------------------------------------------------------
// Kernel 3: GIN layer (R14 config + deeper unrolling for ILP).
// 256 threads, 32 rows/block, grid 256, occupancy 2.
// Phase B 4x4 tile (a = warp broadcast from transposed mT), phase C / OE
// 4x2 tiles. FUSE_OE epilogue reuses mT (sh) and st (su).
// ---------------------------------------------------------------------------
#define MT_S 36    // mT row stride (k-major, 32 rows + pad)
#define ST_S 132   // st row stride (128 + pad)
#define SH_S 68    // sh row stride (64 + pad), aliased onto mT

template <bool FUSE_OE>
__global__ void __launch_bounds__(256, 2)
k_gin(const float* __restrict__ h_in,
      float* __restrict__ h_out,
      const int* __restrict__ nbr,
      const float* __restrict__ Wa, const float* __restrict__ ba,
      const float* __restrict__ Wb, const float* __restrict__ bb,
      const float* __restrict__ W1o, const float* __restrict__ b1o,
      const float* __restrict__ W2o, const float* __restrict__ b2o,
      float* __restrict__ xe) {
    extern __shared__ float sm[];
    float* sWa  = sm;                    // 8192
    float* sWb  = sWa + 8192;            // 8192
    float* sba  = sWb + 8192;            // 128
    float* sbb  = sba + 128;             // 64
    float* mT   = sbb + 64;              // 64*MT_S = 2304 (reused as sh 32*SH_S)
    float* st   = mT + 64 * MT_S;        // 32*ST_S = 4224 (reused as su)
    float* sW1o = st + 32 * ST_S;        // 4096 (FUSE_OE)
    float* sW2o = sW1o + 4096;           // 256
    float* sb1o = sW2o + 256;            // 64
    float* sb2o = sb1o + 64;             // 4

    int tid = threadIdx.x;
    // ---- stage weights (row-major, vectorized) -----------------------------
    {
        const float4* Wa4 = (const float4*)Wa;
        const float4* Wb4 = (const float4*)Wb;
        float4* dA = (float4*)sWa;
        float4* dB = (float4*)sWb;
#pragma unroll
        for (int i = 0; i < 8; ++i) {
            dA[tid + i * 256] = Wa4[tid + i * 256];
            dB[tid + i * 256] = Wb4[tid + i * 256];
        }
        if (tid < 128) sba[tid] = ba[tid];
        if (tid < 64)  sbb[tid] = bb[tid];
        if (FUSE_OE) {
            const float4* W1o4 = (const float4*)W1o;
            float4* d3 = (float4*)sW1o;
#pragma unroll
            for (int i = 0; i < 4; ++i) d3[tid + i * 256] = W1o4[tid + i * 256];
            sW2o[tid] = W2o[tid];        // 256 floats exactly
            if (tid < 64) sb1o[tid] = b1o[tid];
            if (tid < 4)  sb2o[tid] = b2o[tid];
        }
    }

    int base = blockIdx.x * 32;

    // ---- Gather: m = h_i + sum of 15 neighbors -> mT[k][row] ---------------
    {
        int r   = tid >> 3;              // 0..31
        int oct = tid & 7;
        int i   = base + r;
        const float4* h4 = (const float4*)h_in;
        const int* nb = &nbr[i * KK];
        float4 a0 = h4[i * 16 + oct * 2];
        float4 a1 = h4[i * 16 + oct * 2 + 1];
#pragma unroll
        for (int s = 0; s < KK; ++s) {
            int j = nb[s];
            float4 v0 = h4[j * 16 + oct * 2];
            float4 v1 = h4[j * 16 + oct * 2 + 1];
            a0.x += v0.x; a0.y += v0.y; a0.z += v0.z; a0.w += v0.w;
            a1.x += v1.x; a1.y += v1.y; a1.z += v1.z; a1.w += v1.w;
        }
        int k0 = oct * 8;
        mT[(k0 + 0) * MT_S + r] = a0.x;
        mT[(k0 + 1) * MT_S + r] = a0.y;
        mT[(k0 + 2) * MT_S + r] = a0.z;
        mT[(k0 + 3) * MT_S + r] = a0.w;
        mT[(k0 + 4) * MT_S + r] = a1.x;
        mT[(k0 + 5) * MT_S + r] = a1.y;
        mT[(k0 + 6) * MT_S + r] = a1.z;
        mT[(k0 + 7) * MT_S + r] = a1.w;
    }
    __syncthreads();

    int r0 = (tid >> 5) * 4;            // warp-uniform row base (0..28)
    int cx = tid & 31;

    // ---- Phase B: t = relu(m @ Wa + ba), thread tile 4x4, 2-deep pipeline --
    {
        int c0 = cx * 4;
        float acc[4][4];
#pragma unroll
        for (int i = 0; i < 4; ++i)
#pragma unroll
            for (int c = 0; c < 4; ++c) acc[i][c] = sba[c0 + c];

        float4 a0 = *(const float4*)&mT[0 * MT_S + r0];
        float4 b0 = *(const float4*)&sWa[0 * HIDD + c0];
#pragma unroll 16
        for (int k = 0; k < 64; ++k) {
            float4 a = a0, b = b0;
            if (k + 1 < 64) {                                  // load-ahead
                a0 = *(const float4*)&mT[(k + 1) * MT_S + r0];
                b0 = *(const float4*)&sWa[(k + 1) * HIDD + c0];
            }
            acc[0][0] += a.x * b.x; acc[0][1] += a.x * b.y;
            acc[0][2] += a.x * b.z; acc[0][3] += a.x * b.w;
            acc[1][0] += a.y * b.x; acc[1][1] += a.y * b.y;
            acc[1][2] += a.y * b.z; acc[1][3] += a.y * b.w;
            acc[2][0] += a.z * b.x; acc[2][1] += a.z * b.y;
            acc[2][2] += a.z * b.z; acc[2][3] += a.z * b.w;
            acc[3][0] += a.w * b.x; acc[3][1] += a.w * b.y;
            acc[3][2] += a.w * b.z; acc[3][3] += a.w * b.w;
        }
#pragma unroll
        for (int i = 0; i < 4; ++i) {
            float4 q;
            q.x = fmaxf(acc[i][0], 0.f);
            q.y = fmaxf(acc[i][1], 0.f);
            q.z = fmaxf(acc[i][2], 0.f);
            q.w = fmaxf(acc[i][3], 0.f);
            *(float4*)&st[(r0 + i) * ST_S + c0] = q;
        }
    }
    __syncthreads();

    // ---- Phase C: h_out = h_in + t @ Wb + bb, thread tile 4x2 --------------
    int c1 = cx * 2;
    {
        float acc2[4][2];
#pragma unroll
        for (int i = 0; i < 4; ++i) { acc2[i][0] = sbb[c1]; acc2[i][1] = sbb[c1 + 1]; }

#pragma unroll 8
        for (int k2 = 0; k2 < HIDD; k2 += 4) {
            float4 ar[4];
            float2 bk[4];
#pragma unroll
            for (int i = 0; i < 4; ++i) ar[i] = *(const float4*)&st[(r0 + i) * ST_S + k2];
#pragma unroll
            for (int j = 0; j < 4; ++j) bk[j] = *(const float2*)&sWb[(k2 + j) * LATD + c1];
#pragma unroll
            for (int i = 0; i < 4; ++i) {
                acc2[i][0] += ar[i].x * bk[0].x + ar[i].y * bk[1].x
                            + ar[i].z * bk[2].x + ar[i].w * bk[3].x;
                acc2[i][1] += ar[i].x * bk[0].y + ar[i].y * bk[1].y
                            + ar[i].z * bk[2].y + ar[i].w * bk[3].y;
            }
        }
#pragma unroll
        for (int i = 0; i < 4; ++i) {
            float2 hv = *(const float2*)&h_in[(base + r0 + i) * LATD + c1];
            float2 o;
            o.x = hv.x + acc2[i][0];
            o.y = hv.y + acc2[i][1];
            *(float2*)&h_out[(base + r0 + i) * LATD + c1] = o;
            if (FUSE_OE) *(float2*)&mT[(r0 + i) * SH_S + c1] = o;  // sh = mT reuse
        }
    }

    if (FUSE_OE) {
        __syncthreads();
        // ---- OE1: u = leaky(h @ W1o + b1o), thread tile 4x2 (sh=mT) --------
        float u[4][2];
#pragma unroll
        for (int i = 0; i < 4; ++i) { u[i][0] = sb1o[c1]; u[i][1] = sb1o[c1 + 1]; }
#pragma unroll 8
        for (int k = 0; k < LATD; k += 4) {
            float4 ar[4];
            float2 bk[4];
#pragma unroll
            for (int i = 0; i < 4; ++i) ar[i] = *(const float4*)&mT[(r0 + i) * SH_S + k];
#pragma unroll
            for (int j = 0; j < 4; ++j) bk[j] = *(const float2*)&sW1o[(k + j) * LATD + c1];
#pragma unroll
            for (int i = 0; i < 4; ++i) {
                u[i][0] += ar[i].x * bk[0].x + ar[i].y * bk[1].x
                         + ar[i].z * bk[2].x + ar[i].w * bk[3].x;
                u[i][1] += ar[i].x * bk[0].y + ar[i].y * bk[1].y
                         + ar[i].z * bk[2].y + ar[i].w * bk[3].y;
            }
        }
#pragma unroll
        for (int i = 0; i < 4; ++i) {
            float2 q;
            q.x = (u[i][0] > 0.f) ? u[i][0] : 0.01f * u[i][0];
            q.y = (u[i][1] > 0.f) ? u[i][1] : 0.01f * u[i][1];
            *(float2*)&st[(r0 + i) * ST_S + c1] = q;   // su = st reuse
        }
        __syncthreads();
        // ---- OE2: x_emb = u @ W2o + b2o; 128 threads = (row, feature) ------
        if (tid < 128) {
            int row = tid >> 2;
            int oc  = tid & 3;
            float a = sb2o[oc];
#pragma unroll 16
            for (int k = 0; k < LATD; ++k)
                a += st[row * ST_S + k] * sW2o[k * FOUT + oc];
            xe[(base + row) * FOUT + oc] = a;
        }
    }
}

// ---------------------------------------------------------------------------
extern "C" void kernel_launch(void* const* d_in, const int* in_sizes, int n_in,
                              void* d_out, int out_size) {
    const float* x     = (const float*)d_in[0];
    const float* W_se1 = (const float*)d_in[3];
    const float* b_se1 = (const float*)d_in[4];
    const float* W_se2 = (const float*)d_in[5];
    const float* b_se2 = (const float*)d_in[6];
    const float* W_g1a = (const float*)d_in[7];
    const float* b_g1a = (const float*)d_in[8];
    const float* W_g1b = (const float*)d_in[9];
    const float* b_g1b = (const float*)d_in[10];
    const float* W_g2a = (const float*)d_in[11];
    const float* b_g2a = (const float*)d_in[12];
    const float* W_g2b = (const float*)d_in[13];
    const float* b_g2b = (const float*)d_in[14];
    const float* W_oe1 = (const float*)d_in[15];
    const float* b_oe1 = (const float*)d_in[16];
    const float* W_oe2 = (const float*)d_in[17];
    const float* b_oe2 = (const float*)d_in[18];

    float* out    = (float*)d_out;
    float* out_h  = out;
    float* out_xe = out + XE_OFF;
    float* out_ei = out + EI_OFF;

    void *p_h0, *p_h1, *p_nbr, *p_pos;
    cudaGetSymbolAddress(&p_h0, g_h0);
    cudaGetSymbolAddress(&p_h1, g_h1);
    cudaGetSymbolAddress(&p_nbr, g_nbr);
    cudaGetSymbolAddress(&p_pos, g_pos);
    float*  h0  = (float*)p_h0;
    float*  h1  = (float*)p_h1;
    int*    nb  = (int*)p_nbr;
    float4* pos = (float4*)p_pos;

    static const size_t gin_smem_base =
        (size_t)(8192 + 8192 + 128 + 64 + 64 * MT_S + 32 * ST_S) * sizeof(float);
    static const size_t gin_smem_oe = gin_smem_base +
        (size_t)(4096 + 256 + 64 + 4) * sizeof(float);
    cudaFuncSetAttribute(k_gin<false>, cudaFuncAttributeMaxDynamicSharedMemorySize,
                         (int)gin_smem_base);
    cudaFuncSetAttribute(k_gin<true>, cudaFuncAttributeMaxDynamicSharedMemorySize,
                         (int)gin_smem_oe);

    // 1) space_emb -> h0 (+ positions)
    k_space_emb<<<NN / 32, 128>>>(x, W_se1, b_se1, W_se2, b_se2, h0, pos);
    // 2) kNN, 1 warp/query -> nbr, ei
    k_knn<<<GEV * 8, 1024>>>(pos, nb, out_ei);
    // 3) GIN layer 1: h0 -> h1
    k_gin<false><<<NN / 32, 256, gin_smem_base>>>(h0, h1, nb,
        W_g1a, b_g1a, W_g1b, b_g1b, nullptr, nullptr, nullptr, nullptr, nullptr);
    // 4) GIN layer 2 + fused out_emb: h1 -> d_out (h), x_emb -> d_out
    k_gin<true><<<NN / 32, 256, gin_smem_oe>>>(h1, out_h, nb,
        W_g2a, b_g2a, W_g2b, b_g2b, W_oe1, b_oe1, W_oe2, b_oe2, out_xe);
}